// round 6
// baseline (speedup 1.0000x reference)
#include <cuda_runtime.h>

// Problem constants (fixed by the reference setup)
#define BZ_ 8
#define NF_ 10000
#define D_  16
#define H_  512
#define W_  512
#define HW_ (H_ * W_)        // 262144 = 2^18
#define NPIX (BZ_ * HW_)     // 2097152
#define CH_ (D_ + 1)         // 17 output channels
#define TPB 256
#define PPB 256              // pixels per block: 8 warps x 32 px

__global__ void __launch_bounds__(TPB, 5)     // <=51 regs -> 62.5% occupancy cap
render_kernel(const float4* __restrict__ attrs,   // [BZ*NF, 12] float4 (3 verts x 16 floats)
              const float*  __restrict__ baryw,   // [BZ, H, W, 3]
              const int*    __restrict__ tri,     // [BZ, H, W]
              float*        __restrict__ out)     // [BZ, 17, H, W]
{
    const int lane = threadIdx.x & 31;
    const int q    = lane & 3;                     // channel slice 4q..4q+3
    const int g    = lane >> 2;                    // pixel group within warp
    const int warp = threadIdx.x >> 5;
    const int base = blockIdx.x * PPB + warp * 32; // warp's first pixel (mult of 32)
    const int p0   = base + 4 * g;                 // my 4 consecutive pixels

    // ---- coalesced meta loads ----
    const int4 t4 = *(const int4*)(tri + p0);                      // 4 triangle ids
    const float4* bb = (const float4*)(baryw + 3 * p0);            // 12 floats, 16B aligned
    const float4 b0 = bb[0], b1 = bb[1], b2 = bb[2];

    float4 acc[4];

    #pragma unroll
    for (int s = 0; s < 4; s++) {
        const int t = (s == 0) ? t4.x : (s == 1) ? t4.y : (s == 2) ? t4.z : t4.w;
        const float v = (t < 0) ? 0.0f : 1.0f;
        const int  it = (t < 0) ? 0 : t;

        // per-slot barycentric weights straight from b0..b2 (flat [px][3] layout)
        float w0 = (s == 0) ? b0.x : (s == 1) ? b0.w : (s == 2) ? b1.z : b2.y;
        float w1 = (s == 0) ? b0.y : (s == 1) ? b1.x : (s == 2) ? b1.w : b2.z;
        float w2 = (s == 0) ? b0.z : (s == 1) ? b1.y : (s == 2) ? b2.x : b2.w;
        w0 *= v; w1 *= v; w2 *= v;                 // branchless background

        // my 64B-aligned 16B chunks of this face
        const float4* vp = attrs + it * 12 + q;
        const float4 a = vp[0];
        const float4 b = vp[4];
        const float4 c = vp[8];

        float4 r;
        r.x = fmaf(w0, a.x, fmaf(w1, b.x, w2 * c.x));
        r.y = fmaf(w0, a.y, fmaf(w1, b.y, w2 * c.y));
        r.z = fmaf(w0, a.z, fmaf(w1, b.z, w2 * c.z));
        r.w = fmaf(w0, a.w, fmaf(w1, b.w, w2 * c.w));
        acc[s] = r;
    }

    // ---- stores: register transpose -> one STG.128 per channel (single plane) ----
    // 32-bit byte offsets (out spans 142.6MB < 4GB) to cut register pressure
    const int n    = base >> 18;                   // base / HW_
    const int pix0 = (base & (HW_ - 1)) + 4 * g;
    char* ob = (char*)out + (unsigned)(n * CH_ * HW_ + pix0) * 4u;
    const unsigned plane = (unsigned)HW_ * 4u;     // bytes per channel plane

    *(float4*)(ob + (4 * q + 0) * plane) = make_float4(acc[0].x, acc[1].x, acc[2].x, acc[3].x);
    *(float4*)(ob + (4 * q + 1) * plane) = make_float4(acc[0].y, acc[1].y, acc[2].y, acc[3].y);
    *(float4*)(ob + (4 * q + 2) * plane) = make_float4(acc[0].z, acc[1].z, acc[2].z, acc[3].z);
    *(float4*)(ob + (4 * q + 3) * plane) = make_float4(acc[0].w, acc[1].w, acc[2].w, acc[3].w);

    if (q == 0) {
        *(float4*)(ob + D_ * plane) = make_float4(
            (t4.x < 0) ? 0.0f : 1.0f,
            (t4.y < 0) ? 0.0f : 1.0f,
            (t4.z < 0) ? 0.0f : 1.0f,
            (t4.w < 0) ? 0.0f : 1.0f);             // visibility channel
    }
}

extern "C" void kernel_launch(void* const* d_in, const int* in_sizes, int n_in,
                              void* d_out, int out_size)
{
    const float4* attrs = (const float4*)d_in[0];
    const float*  baryw = (const float*)d_in[1];
    const int*    tri   = (const int*)d_in[2];
    float*        out   = (float*)d_out;

    render_kernel<<<NPIX / PPB, TPB>>>(attrs, baryw, tri, out);
}

// round 7
// speedup vs baseline: 1.0393x; 1.0393x over previous
#include <cuda_runtime.h>

// Problem constants (fixed by the reference setup)
#define BZ_ 8
#define NF_ 10000
#define D_  16
#define H_  512
#define W_  512
#define HW_ (H_ * W_)        // 262144 = 2^18
#define NPIX (BZ_ * HW_)     // 2097152
#define CH_ (D_ + 1)         // 17 output channels
#define TPB 256
#define PPB 256              // pixels per block: 8 warps x 32 px

__global__ void __launch_bounds__(TPB, 3)     // <=85 regs: room for 12 in-flight float4 gathers
render_kernel(const float4* __restrict__ attrs,   // [BZ*NF, 12] float4 (3 verts x 16 floats)
              const float*  __restrict__ baryw,   // [BZ, H, W, 3]
              const int*    __restrict__ tri,     // [BZ, H, W]
              float*        __restrict__ out)     // [BZ, 17, H, W]
{
    const int lane = threadIdx.x & 31;
    const int q    = lane & 3;                     // channel slice 4q..4q+3
    const int g    = lane >> 2;                    // pixel group within warp
    const int warp = threadIdx.x >> 5;
    const int base = blockIdx.x * PPB + warp * 32; // warp's first pixel (mult of 32)
    const int p0   = base + 4 * g;                 // my 4 consecutive pixels

    // ---- phase 1: ALL loads issued up front (max MLP) ----
    const int4 t4 = *(const int4*)(tri + p0);                      // 4 triangle ids

    const int i0 = (t4.x < 0) ? 0 : t4.x;
    const int i1 = (t4.y < 0) ? 0 : t4.y;
    const int i2 = (t4.z < 0) ? 0 : t4.z;
    const int i3 = (t4.w < 0) ? 0 : t4.w;

    const float4* v0 = attrs + i0 * 12 + q;
    const float4* v1 = attrs + i1 * 12 + q;
    const float4* v2 = attrs + i2 * 12 + q;
    const float4* v3 = attrs + i3 * 12 + q;

    // 12 independent 16B gathers in flight
    const float4 a0 = v0[0], m0 = v0[4], c0 = v0[8];
    const float4 a1 = v1[0], m1 = v1[4], c1 = v1[8];
    const float4 a2 = v2[0], m2 = v2[4], c2 = v2[8];
    const float4 a3 = v3[0], m3 = v3[4], c3 = v3[8];

    const float4* bb = (const float4*)(baryw + 3 * p0);            // 12 floats, 16B aligned
    const float4 b0 = bb[0], b1 = bb[1], b2 = bb[2];

    // ---- phase 2: weights (branchless background) ----
    const float e0 = (t4.x < 0) ? 0.0f : 1.0f;
    const float e1 = (t4.y < 0) ? 0.0f : 1.0f;
    const float e2 = (t4.z < 0) ? 0.0f : 1.0f;
    const float e3 = (t4.w < 0) ? 0.0f : 1.0f;

    const float w00 = b0.x * e0, w01 = b0.y * e0, w02 = b0.z * e0;
    const float w10 = b0.w * e1, w11 = b1.x * e1, w12 = b1.y * e1;
    const float w20 = b1.z * e2, w21 = b1.w * e2, w22 = b2.x * e2;
    const float w30 = b2.y * e3, w31 = b2.z * e3, w32 = b2.w * e3;

    // ---- phase 3: blend ----
    float4 r0, r1, r2, r3;
    r0.x = fmaf(w00, a0.x, fmaf(w01, m0.x, w02 * c0.x));
    r0.y = fmaf(w00, a0.y, fmaf(w01, m0.y, w02 * c0.y));
    r0.z = fmaf(w00, a0.z, fmaf(w01, m0.z, w02 * c0.z));
    r0.w = fmaf(w00, a0.w, fmaf(w01, m0.w, w02 * c0.w));
    r1.x = fmaf(w10, a1.x, fmaf(w11, m1.x, w12 * c1.x));
    r1.y = fmaf(w10, a1.y, fmaf(w11, m1.y, w12 * c1.y));
    r1.z = fmaf(w10, a1.z, fmaf(w11, m1.z, w12 * c1.z));
    r1.w = fmaf(w10, a1.w, fmaf(w11, m1.w, w12 * c1.w));
    r2.x = fmaf(w20, a2.x, fmaf(w21, m2.x, w22 * c2.x));
    r2.y = fmaf(w20, a2.y, fmaf(w21, m2.y, w22 * c2.y));
    r2.z = fmaf(w20, a2.z, fmaf(w21, m2.z, w22 * c2.z));
    r2.w = fmaf(w20, a2.w, fmaf(w21, m2.w, w22 * c2.w));
    r3.x = fmaf(w30, a3.x, fmaf(w31, m3.x, w32 * c3.x));
    r3.y = fmaf(w30, a3.y, fmaf(w31, m3.y, w32 * c3.y));
    r3.z = fmaf(w30, a3.z, fmaf(w31, m3.z, w32 * c3.z));
    r3.w = fmaf(w30, a3.w, fmaf(w31, m3.w, w32 * c3.w));

    // ---- phase 4: stores, register transpose -> one STG.128 per channel ----
    const int n    = base >> 18;                   // base / HW_
    const int pix0 = (base & (HW_ - 1)) + 4 * g;
    float* op = out + (size_t)n * CH_ * HW_ + pix0;

    *(float4*)(op + (size_t)(4 * q + 0) * HW_) = make_float4(r0.x, r1.x, r2.x, r3.x);
    *(float4*)(op + (size_t)(4 * q + 1) * HW_) = make_float4(r0.y, r1.y, r2.y, r3.y);
    *(float4*)(op + (size_t)(4 * q + 2) * HW_) = make_float4(r0.z, r1.z, r2.z, r3.z);
    *(float4*)(op + (size_t)(4 * q + 3) * HW_) = make_float4(r0.w, r1.w, r2.w, r3.w);

    if (q == 0)
        *(float4*)(op + (size_t)D_ * HW_) = make_float4(e0, e1, e2, e3);  // visibility
}

extern "C" void kernel_launch(void* const* d_in, const int* in_sizes, int n_in,
                              void* d_out, int out_size)
{
    const float4* attrs = (const float4*)d_in[0];
    const float*  baryw = (const float*)d_in[1];
    const int*    tri   = (const int*)d_in[2];
    float*        out   = (float*)d_out;

    render_kernel<<<NPIX / PPB, TPB>>>(attrs, baryw, tri, out);
}